// round 1
// baseline (speedup 1.0000x reference)
#include <cuda_runtime.h>

// Problem constants (fixed dataset):
//   x      [2, 200000, 32]  fp32
//   pos    [2, 200000, 3]   fp32  (uniform [0,1))
//   kernel [3,3,3,32,32]    fp32  (o-major: [o][ci][co], o = oi*9+oj*3+ok)
//   bias   [32]             fp32
//   out    [2, 32, 66,66,66] fp32
#define NPART   400000      // B*N
#define NPERB   200000      // N
#define DD      66
#define HWP     4356        // 66*66
#define DHW     287496      // 66*66*66
#define PT      32          // particles per warp tile
#define NTILES  12500       // NPART / PT

// Channel-last scratch grid [2*DHW][32] for coalesced v4 atomics.
__device__ float g_scratch[(size_t)2 * DHW * 32];   // 73.6 MB

// ---------------------------------------------------------------------------
// Zero the scratch grid (must run every launch; graph-capturable kernel).
// ---------------------------------------------------------------------------
__global__ void zero_scratch_kernel() {
    const size_t n4 = (size_t)2 * DHW * 32 / 4;     // 4,599,936 float4
    float4* p = reinterpret_cast<float4*>(g_scratch);
    for (size_t i = (size_t)blockIdx.x * blockDim.x + threadIdx.x;
         i < n4; i += (size_t)gridDim.x * blockDim.x) {
        p[i] = make_float4(0.f, 0.f, 0.f, 0.f);
    }
}

// ---------------------------------------------------------------------------
// Main scatter kernel.
// One warp handles a tile of PT=32 particles for all 27 stencil offsets,
// processed as 9 groups of 3 (oi,oj fixed; ok=0,1,2).
// Lane c owns output channel c; K for the 3 offsets lives in registers as
// f32x2 pairs over the Ci dimension; x is broadcast from smem via LDS.128.
// Dot products use packed fma.rn.f32x2 (2x fp32 throughput on sm_103a).
// Epilogue: shuffle-gather 4 channels into lane c%4==0 and issue one
// 128-bit atomicAdd(float4*) per 4 channels (4x fewer REDs, one 128B line
// per warp-offset).
// ---------------------------------------------------------------------------
__global__ __launch_bounds__(256, 1) void scatter_kernel(
    const float* __restrict__ x,
    const float* __restrict__ pos,
    const float* __restrict__ kern,
    const float* __restrict__ bias)
{
    __shared__ float xs[8][PT][36];   // padded row (36 floats) -> fewer STS conflicts
    __shared__ float ws[8][PT][9];    // B-spline weights per dim
    __shared__ int   nb[8][PT];       // base node index (incl. batch offset)

    const int w    = threadIdx.x >> 5;
    const int lane = threadIdx.x & 31;
    const int tile = blockIdx.x * 8 + w;
    if (tile >= NTILES) return;       // warp-uniform exit (no block syncs used)
    const int p0 = tile * PT;

    // ---- stage: one particle per lane ----
    {
        const int j   = lane;
        const int pid = p0 + j;
        const float4* xp = reinterpret_cast<const float4*>(x + (size_t)pid * 32);
        float4* xd = reinterpret_cast<float4*>(&xs[w][j][0]);
#pragma unroll
        for (int t = 0; t < 8; ++t) xd[t] = xp[t];

        const float px = pos[pid * 3 + 0] * 64.f;
        const float py = pos[pid * 3 + 1] * 64.f;
        const float pz = pos[pid * 3 + 2] * 64.f;
        const int bx = (int)px, by = (int)py, bz = (int)pz;
        const float fx = px - (float)bx - 0.5f;
        const float fy = py - (float)by - 0.5f;
        const float fz = pz - (float)bz - 0.5f;
        ws[w][j][0] = 0.5f * (0.5f - fx) * (0.5f - fx);
        ws[w][j][1] = 0.75f - fx * fx;
        ws[w][j][2] = 0.5f * (0.5f + fx) * (0.5f + fx);
        ws[w][j][3] = 0.5f * (0.5f - fy) * (0.5f - fy);
        ws[w][j][4] = 0.75f - fy * fy;
        ws[w][j][5] = 0.5f * (0.5f + fy) * (0.5f + fy);
        ws[w][j][6] = 0.5f * (0.5f - fz) * (0.5f - fz);
        ws[w][j][7] = 0.75f - fz * fz;
        ws[w][j][8] = 0.5f * (0.5f + fz) * (0.5f + fz);
        const int b = (pid >= NPERB) ? 1 : 0;
        nb[w][j] = b * DHW + bx * HWP + by * DD + bz;
    }
    __syncwarp();

    const float bc = bias[lane];

    for (int oij = 0; oij < 9; ++oij) {
        const int oi = oij / 3, oj = oij % 3;

        // K[3 offsets][16 f32x2 pairs over ci] for this lane's channel.
        unsigned long long kk[3][16];
#pragma unroll
        for (int ok = 0; ok < 3; ++ok) {
            const float* kb = kern + (size_t)(oij * 3 + ok) * 1024 + lane;
#pragma unroll
            for (int t = 0; t < 16; ++t) {
                const float ke = kb[(2 * t) * 32];
                const float ko = kb[(2 * t + 1) * 32];
                asm("mov.b64 %0, {%1, %2};" : "=l"(kk[ok][t]) : "f"(ke), "f"(ko));
            }
        }
        const int obase = oi * HWP + oj * DD;

        for (int j = 0; j < PT; ++j) {
            const float4* xq = reinterpret_cast<const float4*>(&xs[w][j][0]);
            unsigned long long y0 = 0ull, y1 = 0ull, y2 = 0ull;
#pragma unroll
            for (int t = 0; t < 8; ++t) {
                const float4 xv = xq[t];                    // broadcast LDS.128
                unsigned long long xa, xb;
                asm("mov.b64 %0, {%1, %2};" : "=l"(xa) : "f"(xv.x), "f"(xv.y));
                asm("mov.b64 %0, {%1, %2};" : "=l"(xb) : "f"(xv.z), "f"(xv.w));
                asm("fma.rn.f32x2 %0, %1, %2, %0;" : "+l"(y0) : "l"(xa), "l"(kk[0][2 * t]));
                asm("fma.rn.f32x2 %0, %1, %2, %0;" : "+l"(y0) : "l"(xb), "l"(kk[0][2 * t + 1]));
                asm("fma.rn.f32x2 %0, %1, %2, %0;" : "+l"(y1) : "l"(xa), "l"(kk[1][2 * t]));
                asm("fma.rn.f32x2 %0, %1, %2, %0;" : "+l"(y1) : "l"(xb), "l"(kk[1][2 * t + 1]));
                asm("fma.rn.f32x2 %0, %1, %2, %0;" : "+l"(y2) : "l"(xa), "l"(kk[2][2 * t]));
                asm("fma.rn.f32x2 %0, %1, %2, %0;" : "+l"(y2) : "l"(xb), "l"(kk[2][2 * t + 1]));
            }
            const float wij  = ws[w][j][oi] * ws[w][j][3 + oj];
            const int   node = nb[w][j] + obase;
            unsigned long long yy[3] = {y0, y1, y2};
#pragma unroll
            for (int ok = 0; ok < 3; ++ok) {
                float lo, hi;
                asm("mov.b64 {%0, %1}, %2;" : "=f"(lo), "=f"(hi) : "l"(yy[ok]));
                const float val = (wij * ws[w][j][6 + ok]) * (lo + hi + bc);
                const float v1 = __shfl_down_sync(0xffffffffu, val, 1);
                const float v2 = __shfl_down_sync(0xffffffffu, val, 2);
                const float v3 = __shfl_down_sync(0xffffffffu, val, 3);
                if ((lane & 3) == 0) {
                    float* dst = g_scratch + (size_t)(node + ok) * 32 + lane;
                    atomicAdd(reinterpret_cast<float4*>(dst),
                              make_float4(val, v1, v2, v3));
                }
            }
        }
    }
}

// ---------------------------------------------------------------------------
// Transpose scratch [b][node][c] -> out [b][c][node], fully overwriting out.
// ---------------------------------------------------------------------------
__global__ void transpose_kernel(float* __restrict__ out) {
    __shared__ float t[32][33];
    const int nd0 = blockIdx.x * 32;
    const int b   = blockIdx.y;
    const int tx  = threadIdx.x;      // 32
    const int ty  = threadIdx.y;      // 8
#pragma unroll
    for (int k = 0; k < 4; ++k) {
        const int nd = nd0 + ty + k * 8;
        if (nd < DHW)
            t[ty + k * 8][tx] = g_scratch[((size_t)b * DHW + nd) * 32 + tx];
    }
    __syncthreads();
    const int nd = nd0 + tx;
    if (nd < DHW) {
#pragma unroll
        for (int k = 0; k < 4; ++k) {
            const int c = ty + k * 8;
            out[((size_t)b * 32 + c) * DHW + nd] = t[tx][c];
        }
    }
}

// ---------------------------------------------------------------------------
extern "C" void kernel_launch(void* const* d_in, const int* in_sizes, int n_in,
                              void* d_out, int out_size)
{
    const float* x    = reinterpret_cast<const float*>(d_in[0]);
    const float* pos  = reinterpret_cast<const float*>(d_in[1]);
    const float* kern = reinterpret_cast<const float*>(d_in[2]);
    const float* bias = reinterpret_cast<const float*>(d_in[3]);
    float* out = reinterpret_cast<float*>(d_out);

    zero_scratch_kernel<<<4096, 256>>>();
    scatter_kernel<<<(NTILES + 7) / 8, 256>>>(x, pos, kern, bias);
    transpose_kernel<<<dim3((DHW + 31) / 32, 2), dim3(32, 8)>>>(out);
}

// round 2
// speedup vs baseline: 1.3099x; 1.3099x over previous
#include <cuda_runtime.h>

// Problem constants (fixed dataset):
//   x      [2, 200000, 32]  fp32
//   pos    [2, 200000, 3]   fp32  (uniform [0,1))
//   kernel [3,3,3,32,32]    fp32  (o-major: [o][ci][co], o = oi*9+oj*3+ok)
//   bias   [32]             fp32
//   out    [2, 32, 66,66,66] fp32
#define NPART   400000      // B*N
#define NPERB   200000      // N
#define DD      66
#define HWP     4356        // 66*66
#define DHW     287496      // 66*66*66
#define PT      32          // particles per warp tile
#define NTILES  12500       // NPART / PT
#define NW      4           // warps per block

// Channel-last scratch grid [2*DHW][32] for coalesced v4 atomics.
__device__ float g_scratch[(size_t)2 * DHW * 32];   // 73.6 MB

// ---------------------------------------------------------------------------
// Zero the scratch grid (runs every launch; graph-capturable).
// ---------------------------------------------------------------------------
__global__ void zero_scratch_kernel() {
    const size_t n4 = (size_t)2 * DHW * 32 / 4;     // 4,599,936 float4
    float4* p = reinterpret_cast<float4*>(g_scratch);
    for (size_t i = (size_t)blockIdx.x * blockDim.x + threadIdx.x;
         i < n4; i += (size_t)gridDim.x * blockDim.x) {
        p[i] = make_float4(0.f, 0.f, 0.f, 0.f);
    }
}

// ---------------------------------------------------------------------------
// Scatter kernel. One warp = tile of 32 particles, 27 offsets as 9 groups of
// 3 (oi,oj fixed; ok=0,1,2). Lane c owns channel c; K for the 3 ok lives in
// registers as f32x2 pairs over ci; x broadcast from smem via LDS.128; dot
// products via packed fma.rn.f32x2.
// Epilogue (new in R2): the 3 ok-values hit nodes node..node+2, i.e. 96
// CONSECUTIVE floats of the channel-last scratch. All 32 lanes STS their 3
// values into a 96-float warp buffer, one __syncwarp, then lanes 0..23 issue
// ONE LDS.128 + ONE 24-lane float4 atomicAdd covering all 384 bytes.
// No shuffles, 3x fewer RED instructions, perfectly coalesced lines.
// ---------------------------------------------------------------------------
__global__ __launch_bounds__(NW * 32) void scatter_kernel(
    const float* __restrict__ x,
    const float* __restrict__ pos,
    const float* __restrict__ kern,
    const float* __restrict__ bias)
{
    __shared__ float xs[NW][PT][36];               // padded rows
    __shared__ float ws[NW][PT][9];                // B-spline weights per dim
    __shared__ int   nb[NW][PT];                   // base node (incl. batch)
    __shared__ __align__(16) float vbuf[NW][2][96]; // parity-buffered epilogue

    const int w    = threadIdx.x >> 5;
    const int lane = threadIdx.x & 31;
    const int tile = blockIdx.x * NW + w;
    if (tile >= NTILES) return;                    // warp-uniform exit
    const int p0 = tile * PT;

    // ---- stage: one particle per lane ----
    {
        const int j   = lane;
        const int pid = p0 + j;
        const float4* xp = reinterpret_cast<const float4*>(x + (size_t)pid * 32);
        float4* xd = reinterpret_cast<float4*>(&xs[w][j][0]);
#pragma unroll
        for (int t = 0; t < 8; ++t) xd[t] = xp[t];

        const float px = pos[pid * 3 + 0] * 64.f;
        const float py = pos[pid * 3 + 1] * 64.f;
        const float pz = pos[pid * 3 + 2] * 64.f;
        const int bx = (int)px, by = (int)py, bz = (int)pz;
        const float fx = px - (float)bx - 0.5f;
        const float fy = py - (float)by - 0.5f;
        const float fz = pz - (float)bz - 0.5f;
        ws[w][j][0] = 0.5f * (0.5f - fx) * (0.5f - fx);
        ws[w][j][1] = 0.75f - fx * fx;
        ws[w][j][2] = 0.5f * (0.5f + fx) * (0.5f + fx);
        ws[w][j][3] = 0.5f * (0.5f - fy) * (0.5f - fy);
        ws[w][j][4] = 0.75f - fy * fy;
        ws[w][j][5] = 0.5f * (0.5f + fy) * (0.5f + fy);
        ws[w][j][6] = 0.5f * (0.5f - fz) * (0.5f - fz);
        ws[w][j][7] = 0.75f - fz * fz;
        ws[w][j][8] = 0.5f * (0.5f + fz) * (0.5f + fz);
        const int b = (pid >= NPERB) ? 1 : 0;
        nb[w][j] = b * DHW + bx * HWP + by * DD + bz;
    }
    __syncwarp();

    const float bc = bias[lane];

    for (int oij = 0; oij < 9; ++oij) {
        const int oi = oij / 3, oj = oij % 3;

        // K[3 ok][16 f32x2 pairs over ci] for this lane's channel (coalesced LDG).
        unsigned long long kk[3][16];
#pragma unroll
        for (int ok = 0; ok < 3; ++ok) {
            const float* kb = kern + (size_t)(oij * 3 + ok) * 1024 + lane;
#pragma unroll
            for (int t = 0; t < 16; ++t) {
                const float ke = kb[(2 * t) * 32];
                const float ko = kb[(2 * t + 1) * 32];
                asm("mov.b64 %0, {%1, %2};" : "=l"(kk[ok][t]) : "f"(ke), "f"(ko));
            }
        }
        const int obase = oi * HWP + oj * DD;

        for (int j = 0; j < PT; ++j) {
            const float4* xq = reinterpret_cast<const float4*>(&xs[w][j][0]);
            unsigned long long y0 = 0ull, y1 = 0ull, y2 = 0ull;
#pragma unroll
            for (int t = 0; t < 8; ++t) {
                const float4 xv = xq[t];                    // broadcast LDS.128
                unsigned long long xa, xb;
                asm("mov.b64 %0, {%1, %2};" : "=l"(xa) : "f"(xv.x), "f"(xv.y));
                asm("mov.b64 %0, {%1, %2};" : "=l"(xb) : "f"(xv.z), "f"(xv.w));
                asm("fma.rn.f32x2 %0, %1, %2, %0;" : "+l"(y0) : "l"(xa), "l"(kk[0][2 * t]));
                asm("fma.rn.f32x2 %0, %1, %2, %0;" : "+l"(y0) : "l"(xb), "l"(kk[0][2 * t + 1]));
                asm("fma.rn.f32x2 %0, %1, %2, %0;" : "+l"(y1) : "l"(xa), "l"(kk[1][2 * t]));
                asm("fma.rn.f32x2 %0, %1, %2, %0;" : "+l"(y1) : "l"(xb), "l"(kk[1][2 * t + 1]));
                asm("fma.rn.f32x2 %0, %1, %2, %0;" : "+l"(y2) : "l"(xa), "l"(kk[2][2 * t]));
                asm("fma.rn.f32x2 %0, %1, %2, %0;" : "+l"(y2) : "l"(xb), "l"(kk[2][2 * t + 1]));
            }
            const float wij = ws[w][j][oi] * ws[w][j][3 + oj];
            const int  node = nb[w][j] + obase;
            float* vb = &vbuf[w][j & 1][0];

            {   // ok = 0,1,2 -> vbuf[ok*32 + lane]
                float lo, hi;
                asm("mov.b64 {%0, %1}, %2;" : "=f"(lo), "=f"(hi) : "l"(y0));
                vb[lane]      = (wij * ws[w][j][6]) * (lo + hi + bc);
                asm("mov.b64 {%0, %1}, %2;" : "=f"(lo), "=f"(hi) : "l"(y1));
                vb[32 + lane] = (wij * ws[w][j][7]) * (lo + hi + bc);
                asm("mov.b64 {%0, %1}, %2;" : "=f"(lo), "=f"(hi) : "l"(y2));
                vb[64 + lane] = (wij * ws[w][j][8]) * (lo + hi + bc);
            }
            __syncwarp();
            if (lane < 24) {
                // 96 consecutive scratch floats: (node+ok)*32 + c = node*32 + (ok*32+c)
                const float4 v = *reinterpret_cast<const float4*>(vb + 4 * lane);
                atomicAdd(reinterpret_cast<float4*>(
                              g_scratch + (size_t)node * 32 + 4 * lane), v);
            }
        }
    }
}

// ---------------------------------------------------------------------------
// Transpose scratch [b][node][c] -> out [b][c][node], fully overwriting out.
// ---------------------------------------------------------------------------
__global__ void transpose_kernel(float* __restrict__ out) {
    __shared__ float t[32][33];
    const int nd0 = blockIdx.x * 32;
    const int b   = blockIdx.y;
    const int tx  = threadIdx.x;      // 32
    const int ty  = threadIdx.y;      // 8
#pragma unroll
    for (int k = 0; k < 4; ++k) {
        const int nd = nd0 + ty + k * 8;
        if (nd < DHW)
            t[ty + k * 8][tx] = g_scratch[((size_t)b * DHW + nd) * 32 + tx];
    }
    __syncthreads();
    const int nd = nd0 + tx;
    if (nd < DHW) {
#pragma unroll
        for (int k = 0; k < 4; ++k) {
            const int c = ty + k * 8;
            out[((size_t)b * 32 + c) * DHW + nd] = t[tx][c];
        }
    }
}

// ---------------------------------------------------------------------------
extern "C" void kernel_launch(void* const* d_in, const int* in_sizes, int n_in,
                              void* d_out, int out_size)
{
    const float* x    = reinterpret_cast<const float*>(d_in[0]);
    const float* pos  = reinterpret_cast<const float*>(d_in[1]);
    const float* kern = reinterpret_cast<const float*>(d_in[2]);
    const float* bias = reinterpret_cast<const float*>(d_in[3]);
    float* out = reinterpret_cast<float*>(d_out);

    zero_scratch_kernel<<<4096, 256>>>();
    scatter_kernel<<<(NTILES + NW - 1) / NW, NW * 32>>>(x, pos, kern, bias);
    transpose_kernel<<<dim3((DHW + 31) / 32, 2), dim3(32, 8)>>>(out);
}

// round 3
// speedup vs baseline: 1.3601x; 1.0383x over previous
#include <cuda_runtime.h>

// Problem constants (fixed dataset):
//   x      [2, 200000, 32]  fp32
//   pos    [2, 200000, 3]   fp32  (uniform [0,1))
//   kernel [3,3,3,32,32]    fp32  (o-major: [o][ci][co], o = oi*9+oj*3+ok)
//   bias   [32]             fp32
//   out    [2, 32, 66,66,66] fp32
#define NPART   400000      // B*N
#define NPERB   200000      // N
#define DD      66
#define HWP     4356        // 66*66
#define DHW     287496      // 66*66*66
#define PT      32          // particles per warp tile
#define NTILES  12500       // NPART / PT
#define NW      4           // warps per block

// Channel-last scratch grid [2*DHW][32] for coalesced v4 atomics.
// Zero-initialized at module load; re-zeroed at the END of every launch
// (after transpose consumes it) so each call starts from zeros.
__device__ float g_scratch[(size_t)2 * DHW * 32];   // 73.6 MB

// ---------------------------------------------------------------------------
// Zero the scratch grid for the NEXT call (runs last in the graph).
// ---------------------------------------------------------------------------
__global__ void zero_scratch_kernel() {
    const size_t n4 = (size_t)2 * DHW * 32 / 4;     // 4,599,936 float4
    float4* p = reinterpret_cast<float4*>(g_scratch);
    for (size_t i = (size_t)blockIdx.x * blockDim.x + threadIdx.x;
         i < n4; i += (size_t)gridDim.x * blockDim.x) {
        p[i] = make_float4(0.f, 0.f, 0.f, 0.f);
    }
}

// ---------------------------------------------------------------------------
// Scatter kernel. One warp = tile of 32 particles, 27 offsets as 9 groups of
// 3 (oi,oj fixed; ok=0,1,2). Lane c owns channel c; K for the 3 ok in regs as
// f32x2 pairs over ci; x broadcast from smem as ulonglong2 (LDS.128, pairs
// feed fma.rn.f32x2 with no repacking).
// Epilogue: batch 4 particles -> 384 consecutive scratch floats per particle
// region; STS all values, one syncwarp, then THREE full-warp float4 REDs
// cover all 4 particles (32 lanes x 16B x 3). 4x fewer syncs than R2.
// ---------------------------------------------------------------------------
__global__ __launch_bounds__(NW * 32) void scatter_kernel(
    const float* __restrict__ x,
    const float* __restrict__ pos,
    const float* __restrict__ kern,
    const float* __restrict__ bias)
{
    __shared__ __align__(16) float xs[NW][PT][36];  // 16B-aligned rows (144B)
    __shared__ float ws[NW][PT][9];                 // B-spline weights per dim
    __shared__ int   nb[NW][PT];                    // base node (incl. batch)
    __shared__ __align__(16) float vbuf[NW][384];   // 4-particle epilogue stage

    const int w    = threadIdx.x >> 5;
    const int lane = threadIdx.x & 31;
    const int tile = blockIdx.x * NW + w;
    if (tile >= NTILES) return;                     // warp-uniform exit
    const int p0 = tile * PT;

    // Loop-invariant epilogue mapping: r-th RED, this lane covers float4
    // f = r*32+lane of the 96-float4 batch -> particle jj = f/24, qoff = f%24.
    int jj_r[3], q4_r[3];
#pragma unroll
    for (int r = 0; r < 3; ++r) {
        const int f = r * 32 + lane;
        jj_r[r] = f / 24;
        q4_r[r] = (f % 24) * 4;                     // float offset in region
    }

    // ---- stage: one particle per lane ----
    {
        const int j   = lane;
        const int pid = p0 + j;
        const float4* xp = reinterpret_cast<const float4*>(x + (size_t)pid * 32);
        float4* xd = reinterpret_cast<float4*>(&xs[w][j][0]);
#pragma unroll
        for (int t = 0; t < 8; ++t) xd[t] = xp[t];

        const float px = pos[pid * 3 + 0] * 64.f;
        const float py = pos[pid * 3 + 1] * 64.f;
        const float pz = pos[pid * 3 + 2] * 64.f;
        const int bx = (int)px, by = (int)py, bz = (int)pz;
        const float fx = px - (float)bx - 0.5f;
        const float fy = py - (float)by - 0.5f;
        const float fz = pz - (float)bz - 0.5f;
        ws[w][j][0] = 0.5f * (0.5f - fx) * (0.5f - fx);
        ws[w][j][1] = 0.75f - fx * fx;
        ws[w][j][2] = 0.5f * (0.5f + fx) * (0.5f + fx);
        ws[w][j][3] = 0.5f * (0.5f - fy) * (0.5f - fy);
        ws[w][j][4] = 0.75f - fy * fy;
        ws[w][j][5] = 0.5f * (0.5f + fy) * (0.5f + fy);
        ws[w][j][6] = 0.5f * (0.5f - fz) * (0.5f - fz);
        ws[w][j][7] = 0.75f - fz * fz;
        ws[w][j][8] = 0.5f * (0.5f + fz) * (0.5f + fz);
        const int b = (pid >= NPERB) ? 1 : 0;
        nb[w][j] = b * DHW + bx * HWP + by * DD + bz;
    }
    __syncwarp();

    const float bc = bias[lane];
    float* const vb = &vbuf[w][0];

    for (int oij = 0; oij < 9; ++oij) {
        const int oi = oij / 3, oj = oij % 3;

        // K[3 ok][16 f32x2 pairs over ci] for this lane's channel.
        unsigned long long kk[3][16];
#pragma unroll
        for (int ok = 0; ok < 3; ++ok) {
            const float* kb = kern + (size_t)(oij * 3 + ok) * 1024 + lane;
#pragma unroll
            for (int t = 0; t < 16; ++t) {
                const float ke = kb[(2 * t) * 32];
                const float ko = kb[(2 * t + 1) * 32];
                asm("mov.b64 %0, {%1, %2};" : "=l"(kk[ok][t]) : "f"(ke), "f"(ko));
            }
        }
        const int obase = oi * HWP + oj * DD;

        for (int j4 = 0; j4 < PT; j4 += 4) {
#pragma unroll
            for (int u = 0; u < 4; ++u) {
                const int j = j4 + u;
                const ulonglong2* xq =
                    reinterpret_cast<const ulonglong2*>(&xs[w][j][0]);
                unsigned long long y0 = 0ull, y1 = 0ull, y2 = 0ull;
#pragma unroll
                for (int t = 0; t < 8; ++t) {
                    const ulonglong2 xv = xq[t];            // LDS.128 broadcast
                    asm("fma.rn.f32x2 %0, %1, %2, %0;" : "+l"(y0) : "l"(xv.x), "l"(kk[0][2 * t]));
                    asm("fma.rn.f32x2 %0, %1, %2, %0;" : "+l"(y0) : "l"(xv.y), "l"(kk[0][2 * t + 1]));
                    asm("fma.rn.f32x2 %0, %1, %2, %0;" : "+l"(y1) : "l"(xv.x), "l"(kk[1][2 * t]));
                    asm("fma.rn.f32x2 %0, %1, %2, %0;" : "+l"(y1) : "l"(xv.y), "l"(kk[1][2 * t + 1]));
                    asm("fma.rn.f32x2 %0, %1, %2, %0;" : "+l"(y2) : "l"(xv.x), "l"(kk[2][2 * t]));
                    asm("fma.rn.f32x2 %0, %1, %2, %0;" : "+l"(y2) : "l"(xv.y), "l"(kk[2][2 * t + 1]));
                }
                const float wij = ws[w][j][oi] * ws[w][j][3 + oj];
                float lo, hi;
                float* vu = vb + u * 96;
                asm("mov.b64 {%0, %1}, %2;" : "=f"(lo), "=f"(hi) : "l"(y0));
                vu[lane]      = (wij * ws[w][j][6]) * (lo + hi + bc);
                asm("mov.b64 {%0, %1}, %2;" : "=f"(lo), "=f"(hi) : "l"(y1));
                vu[32 + lane] = (wij * ws[w][j][7]) * (lo + hi + bc);
                asm("mov.b64 {%0, %1}, %2;" : "=f"(lo), "=f"(hi) : "l"(y2));
                vu[64 + lane] = (wij * ws[w][j][8]) * (lo + hi + bc);
            }
            __syncwarp();
            // Three full-warp float4 REDs cover all 4 particles' 96 floats each.
#pragma unroll
            for (int r = 0; r < 3; ++r) {
                const int node = nb[w][j4 + jj_r[r]] + obase;   // warp-uniform smem read
                const float4 v =
                    *reinterpret_cast<const float4*>(vb + (r * 32 + lane) * 4);
                atomicAdd(reinterpret_cast<float4*>(
                              g_scratch + (size_t)node * 32 + q4_r[r]), v);
            }
            __syncwarp();   // vbuf reuse guard
        }
    }
}

// ---------------------------------------------------------------------------
// Transpose scratch [b][node][c] -> out [b][c][node], fully overwriting out.
// ---------------------------------------------------------------------------
__global__ void transpose_kernel(float* __restrict__ out) {
    __shared__ float t[32][33];
    const int nd0 = blockIdx.x * 32;
    const int b   = blockIdx.y;
    const int tx  = threadIdx.x;      // 32
    const int ty  = threadIdx.y;      // 8
#pragma unroll
    for (int k = 0; k < 4; ++k) {
        const int nd = nd0 + ty + k * 8;
        if (nd < DHW)
            t[ty + k * 8][tx] = g_scratch[((size_t)b * DHW + nd) * 32 + tx];
    }
    __syncthreads();
    const int nd = nd0 + tx;
    if (nd < DHW) {
#pragma unroll
        for (int k = 0; k < 4; ++k) {
            const int c = ty + k * 8;
            out[((size_t)b * 32 + c) * DHW + nd] = t[tx][c];
        }
    }
}

// ---------------------------------------------------------------------------
// Launch order: scatter FIRST (so the ncu capture window lands on it),
// then transpose (consumes scratch), then zero (prepares next call).
// g_scratch is zero at module load, so the first call is also correct.
// ---------------------------------------------------------------------------
extern "C" void kernel_launch(void* const* d_in, const int* in_sizes, int n_in,
                              void* d_out, int out_size)
{
    const float* x    = reinterpret_cast<const float*>(d_in[0]);
    const float* pos  = reinterpret_cast<const float*>(d_in[1]);
    const float* kern = reinterpret_cast<const float*>(d_in[2]);
    const float* bias = reinterpret_cast<const float*>(d_in[3]);
    float* out = reinterpret_cast<float*>(d_out);

    scatter_kernel<<<(NTILES + NW - 1) / NW, NW * 32>>>(x, pos, kern, bias);
    transpose_kernel<<<dim3((DHW + 31) / 32, 2), dim3(32, 8)>>>(out);
    zero_scratch_kernel<<<4096, 256>>>();
}